// round 15
// baseline (speedup 1.0000x reference)
#include <cuda_runtime.h>
#include <math.h>

typedef unsigned long long ull;

#define NB 16
#define NH 64
#define NL 16384
#define NN 64
#define NCD 32
#define NC 8          // chunks per sequence
#define CLEN 2048     // NL / NC
#define PPAD 36       // P row stride (16B-aligned, conflict-free)

// scratch (static __device__ per harness rules)
__device__ float  g_u[(size_t)NB * NH * NL];            // premixed+gelu input
__device__ ull    g_e[(size_t)NB * NH * (NC - 1) * 64]; // chunk end states
__device__ ull    g_s[(size_t)NB * NH * NC * 64];       // entering states
__device__ float2 g_wd[NH * NH];                        // duplicated W pairs

// ---------- packed f32x2 helpers ----------
__device__ __forceinline__ ull fma2(ull a, ull b, ull c) {
    ull d;
    asm("fma.rn.f32x2 %0, %1, %2, %3;" : "=l"(d) : "l"(a), "l"(b), "l"(c));
    return d;
}
__device__ __forceinline__ ull mul2(ull a, ull b) {
    ull d;
    asm("mul.rn.f32x2 %0, %1, %2;" : "=l"(d) : "l"(a), "l"(b));
    return d;
}
union F2U { float2 f; ull u; };
__device__ __forceinline__ ull pack2(float a, float b) { F2U t; t.f = make_float2(a, b); return t.u; }
__device__ __forceinline__ float2 unpack2(ull v) { F2U t; t.u = v; return t.f; }

__device__ __forceinline__ float gelu_exact(float v) {
    return 0.5f * v * (1.0f + erff(v * 0.7071067811865475f));
}

// 16-byte async copy global -> shared (Ampere+ cp.async)
__device__ __forceinline__ void cp_async16(void* smem_dst, const void* gmem_src) {
    unsigned saddr = (unsigned)__cvta_generic_to_shared(smem_dst);
    asm volatile("cp.async.ca.shared.global [%0], [%1], 16;"
                 :: "r"(saddr), "l"(gmem_src) : "memory");
}
__device__ __forceinline__ void cp_async_wait_all() {
    asm volatile("cp.async.commit_group;\n\tcp.async.wait_group 0;" ::: "memory");
}

// w = exp(dt*A) for the two states this lane owns
__device__ __forceinline__ void lane_w(int h, int lane,
                                       const float* __restrict__ log_dt,
                                       const float* __restrict__ log_A_real,
                                       const float* __restrict__ A_imag,
                                       float wr[2], float wi[2])
{
    const float dt = expf(log_dt[h]);
    #pragma unroll
    for (int s = 0; s < 2; s++) {
        int n = 2 * lane + s;
        float Ar = -expf(log_A_real[h * NN + n]);
        float Ai = A_imag[h * NN + n];
        float er = expf(Ar * dt);
        float sn, cs;
        sincosf(Ai * dt, &sn, &cs);
        wr[s] = er * cs;
        wi[s] = er * sn;
    }
}

// =====================================================================
// Kernel 0: one-time duplicated-W table (32KB, L1/L2-resident)
// =====================================================================
__global__ __launch_bounds__(256) void wdup_kernel(const float* __restrict__ W)
{
    for (int i = threadIdx.x; i < NH * NH; i += 256) {
        float wv = W[i];
        g_wd[i] = make_float2(wv, wv);
    }
}

// =====================================================================
// Kernel 1: premix  u = gelu(W x + b)
// x staged via cp.async (64KB smem -> 3 blocks/SM); W pairs read from
// the global g_wd table via __ldg (L1-hot broadcast).
// =====================================================================
__global__ __launch_bounds__(256, 3) void premix_kernel(
    const float* __restrict__ x, const float* __restrict__ b_lin)
{
    extern __shared__ float2 sm2[];
    float2* xs = sm2;            // [NH][128] l-pairs

    const int tid = threadIdx.x;
    const int b   = blockIdx.y;
    const int l0  = blockIdx.x * 256;

    // async-stage x: 4096 x 16B
    const float* xb = x + ((size_t)b * NH) * NL + l0;
    #pragma unroll
    for (int k = 0; k < 16; k++) {
        int i = tid + k * 256;               // 0..4095
        int h = i >> 6, v = i & 63;
        cp_async16((char*)xs + h * 1024 + v * 16, xb + (size_t)h * NL + v * 4);
    }
    cp_async_wait_all();
    __syncthreads();

    const int tg   = tid >> 5;
    const int lane = tid & 31;

    ull acc[8][4];
    #pragma unroll
    for (int j = 0; j < 8; j++)
        #pragma unroll
        for (int p = 0; p < 4; p++) acc[j][p] = 0ULL;

    #pragma unroll 2
    for (int h = 0; h < NH; h += 2) {
        ull xp0[4], xp1[4];
        #pragma unroll
        for (int p = 0; p < 4; p++) {
            xp0[p] = *(const ull*)&xs[h * 128 + lane + 32 * p];
            xp1[p] = *(const ull*)&xs[(h + 1) * 128 + lane + 32 * p];
        }
        #pragma unroll
        for (int j = 0; j < 8; j++) {
            // LDG.128 broadcast from L1-resident duplicated-W table
            float4 wv4 = __ldg((const float4*)&g_wd[(tg * 8 + j) * NH + h]);
            ull wva = pack2(wv4.x, wv4.y);
            ull wvb = pack2(wv4.z, wv4.w);
            #pragma unroll
            for (int p = 0; p < 4; p++) acc[j][p] = fma2(wva, xp0[p], acc[j][p]);
            #pragma unroll
            for (int p = 0; p < 4; p++) acc[j][p] = fma2(wvb, xp1[p], acc[j][p]);
        }
    }

    #pragma unroll
    for (int j = 0; j < 8; j++) {
        int g = tg * 8 + j;
        float bl = b_lin[g];
        float2* ub = (float2*)(g_u + ((size_t)b * NH + g) * NL + l0);
        #pragma unroll
        for (int p = 0; p < 4; p++) {
            float2 v = unpack2(acc[j][p]);
            ub[lane + 32 * p] = make_float2(gelu_exact(v.x + bl), gelu_exact(v.y + bl));
        }
    }
}

// =====================================================================
// Kernel 2: pass 1 — zero-init state recurrence per chunk (chunks 0..NC-2)
// 8-step grouped:  q' = w^8 q + (w^7 u1 + ... + w u7 + u8)
// =====================================================================
__global__ __launch_bounds__(128) void state_kernel(
    const float* __restrict__ log_dt, const float* __restrict__ log_A_real,
    const float* __restrict__ A_imag)
{
    __shared__ __align__(16) float2 Us[4][2][32];

    const int w    = threadIdx.x >> 5;
    const int lane = threadIdx.x & 31;
    const int idx  = blockIdx.x * 4 + w;
    const int bh   = idx / (NC - 1);
    const int c    = idx - bh * (NC - 1);
    const int h    = bh & 63;

    float wr[2], wi[2];
    lane_w(h, lane, log_dt, log_A_real, A_imag, wr, wi);

    float pr[8][2], pi[8][2];
    #pragma unroll
    for (int s = 0; s < 2; s++) { pr[0][s] = wr[s]; pi[0][s] = wi[s]; }
    #pragma unroll
    for (int k = 1; k < 8; k++) {
        #pragma unroll
        for (int s = 0; s < 2; s++) {
            pr[k][s] = pr[k-1][s] * wr[s] - pi[k-1][s] * wi[s];
            pi[k][s] = pr[k-1][s] * wi[s] + pi[k-1][s] * wr[s];
        }
    }
    const ull w1r2 = pack2(pr[0][0], pr[0][1]), w1i2 = pack2(pi[0][0], pi[0][1]);
    const ull w2r2 = pack2(pr[1][0], pr[1][1]), w2i2 = pack2(pi[1][0], pi[1][1]);
    const ull w3r2 = pack2(pr[2][0], pr[2][1]), w3i2 = pack2(pi[2][0], pi[2][1]);
    const ull w4r2 = pack2(pr[3][0], pr[3][1]), w4i2 = pack2(pi[3][0], pi[3][1]);
    const ull w5r2 = pack2(pr[4][0], pr[4][1]), w5i2 = pack2(pi[4][0], pi[4][1]);
    const ull w6r2 = pack2(pr[5][0], pr[5][1]), w6i2 = pack2(pi[5][0], pi[5][1]);
    const ull w7r2 = pack2(pr[6][0], pr[6][1]), w7i2 = pack2(pi[6][0], pi[6][1]);
    const ull w8r2 = pack2(pr[7][0], pr[7][1]), w8i2 = pack2(pi[7][0], pi[7][1]);
    const ull nw8i2 = pack2(-pi[7][0], -pi[7][1]);

    const float* ub = g_u + (size_t)bh * NL + (size_t)c * CLEN;

    float u_cur = ub[lane];
    ull qr = 0ULL, qi = 0ULL;

    for (int l0 = 0; l0 < CLEN; l0 += 32) {
        float2* U = Us[w][(l0 >> 5) & 1];
        U[lane] = make_float2(u_cur, u_cur);
        int nn = (l0 + 32 < CLEN) ? (l0 + 32 + lane) : lane;
        float u_nx = ub[nn];
        __syncwarp();
        #pragma unroll
        for (int m = 0; m < 4; m++) {
            ulonglong2 p01 = *(const ulonglong2*)&U[8*m];
            ulonglong2 p23 = *(const ulonglong2*)&U[8*m + 2];
            ulonglong2 p45 = *(const ulonglong2*)&U[8*m + 4];
            ulonglong2 p67 = *(const ulonglong2*)&U[8*m + 6];
            ull rr = fma2(w7r2, p01.x, fma2(w6r2, p01.y, fma2(w5r2, p23.x,
                     fma2(w4r2, p23.y, fma2(w3r2, p45.x, fma2(w2r2, p45.y,
                     fma2(w1r2, p67.x, p67.y)))))));
            ull ri = fma2(w7i2, p01.x, fma2(w6i2, p01.y, fma2(w5i2, p23.x,
                     fma2(w4i2, p23.y, fma2(w3i2, p45.x, fma2(w2i2, p45.y,
                     mul2(w1i2, p67.x)))))));
            ull nqr = fma2(w8r2, qr, fma2(nw8i2, qi, rr));
            qi      = fma2(w8i2, qr, fma2(w8r2,  qi, ri));
            qr      = nqr;
        }
        u_cur = u_nx;
    }

    ull* ep = g_e + ((size_t)(bh * (NC - 1) + c)) * 64;
    ep[lane]      = qr;
    ep[lane + 32] = qi;
}

// =====================================================================
// Kernel 3: pass 2 — serial combine over chunks (tiny)
// =====================================================================
__global__ __launch_bounds__(128) void combine_kernel(
    const float* __restrict__ log_dt, const float* __restrict__ log_A_real,
    const float* __restrict__ A_imag)
{
    const int w    = threadIdx.x >> 5;
    const int lane = threadIdx.x & 31;
    const int bh   = blockIdx.x * 4 + w;
    const int h    = bh & 63;

    float wr[2], wi[2];
    lane_w(h, lane, log_dt, log_A_real, A_imag, wr, wi);

    float tr[2] = {wr[0], wr[1]}, ti[2] = {wi[0], wi[1]};
    for (int k = 0; k < 11; k++) {
        #pragma unroll
        for (int s = 0; s < 2; s++) {
            float nr = tr[s]*tr[s] - ti[s]*ti[s];
            ti[s] = 2.0f*tr[s]*ti[s];
            tr[s] = nr;
        }
    }

    float sr[2] = {0.f, 0.f}, si[2] = {0.f, 0.f};
    for (int c = 0; c < NC; c++) {
        ull* sp = g_s + ((size_t)(bh * NC + c)) * 64;
        sp[lane]      = pack2(sr[0], sr[1]);
        sp[lane + 32] = pack2(si[0], si[1]);
        if (c < NC - 1) {
            const ull* ep = g_e + ((size_t)(bh * (NC - 1) + c)) * 64;
            float2 er = unpack2(ep[lane]);
            float2 ei = unpack2(ep[lane + 32]);
            float e_r[2] = {er.x, er.y}, e_i[2] = {ei.x, ei.y};
            #pragma unroll
            for (int s = 0; s < 2; s++) {
                float nr = tr[s]*sr[s] - ti[s]*si[s] + e_r[s];
                float ni = tr[s]*si[s] + ti[s]*sr[s] + e_i[s];
                sr[s] = nr; si[s] = ni;
            }
        }
    }
}

// =====================================================================
// Kernel 4: pass 3 — 4-step grouped scan (R12 math, measured best),
// single-buffered U, double-buffered P, branchless taps via shfl,
// fused FiLM + GELU + residual.
// =====================================================================
__global__ __launch_bounds__(128, 5) void scan_kernel(
    const float* __restrict__ x,
    const float* __restrict__ log_dt, const float* __restrict__ log_A_real,
    const float* __restrict__ A_imag, const float* __restrict__ C_re,
    const float* __restrict__ C_im,   const float* __restrict__ Dvec,
    const float* __restrict__ cond,   const float* __restrict__ film_W,
    const float* __restrict__ film_b, const float* __restrict__ res_w,
    float* __restrict__ out)
{
    __shared__ __align__(16) float2 Us[4][32];
    __shared__ __align__(16) float  Ps[4][2][32 * PPAD];

    const int w    = threadIdx.x >> 5;
    const int lane = threadIdx.x & 31;
    const int idx  = blockIdx.x * 4 + w;
    const int bh   = idx >> 3;
    const int c    = idx & 7;
    const int b    = bh >> 6;
    const int h    = bh & 63;

    float wr[2], wi[2];
    lane_w(h, lane, log_dt, log_A_real, A_imag, wr, wi);

    // coef c = 2*C*(w-1)/A
    float cr[2], ci[2];
    #pragma unroll
    for (int s = 0; s < 2; s++) {
        int n = 2 * lane + s;
        float Ar = -expf(log_A_real[h * NN + n]);
        float Ai = A_imag[h * NN + n];
        float Er = wr[s] - 1.0f, Ei = wi[s];
        float inv = 1.0f / (Ar*Ar + Ai*Ai);
        float Fr = (Er*Ar + Ei*Ai) * inv;
        float Fi = (Ei*Ar - Er*Ai) * inv;
        float Cr = C_re[h * NN + n], Ci = C_im[h * NN + n];
        cr[s] = 2.0f * (Cr*Fr - Ci*Fi);
        ci[s] = 2.0f * (Cr*Fi + Ci*Fr);
    }

    // w powers and projected coefs c*w^g
    float w2r[2], w2i[2], w3r[2], w3i[2], w4r[2], w4i[2];
    float c1r[2], c1i[2], c2r[2], c2i[2], c3r[2], c3i[2];
    #pragma unroll
    for (int s = 0; s < 2; s++) {
        w2r[s] = wr[s]*wr[s] - wi[s]*wi[s];   w2i[s] = 2.0f*wr[s]*wi[s];
        w3r[s] = w2r[s]*wr[s] - w2i[s]*wi[s]; w3i[s] = w2r[s]*wi[s] + w2i[s]*wr[s];
        w4r[s] = w2r[s]*w2r[s] - w2i[s]*w2i[s]; w4i[s] = 2.0f*w2r[s]*w2i[s];
        c1r[s] = cr[s]*wr[s]  - ci[s]*wi[s];  c1i[s] = cr[s]*wi[s]  + ci[s]*wr[s];
        c2r[s] = cr[s]*w2r[s] - ci[s]*w2i[s]; c2i[s] = cr[s]*w2i[s] + ci[s]*w2r[s];
        c3r[s] = cr[s]*w3r[s] - ci[s]*w3i[s]; c3i[s] = cr[s]*w3i[s] + ci[s]*w3r[s];
    }
    const ull w1r2 = pack2(wr[0], wr[1]),   w1i2 = pack2(wi[0], wi[1]);
    const ull w2r2 = pack2(w2r[0], w2r[1]), w2i2 = pack2(w2i[0], w2i[1]);
    const ull w3r2 = pack2(w3r[0], w3r[1]), w3i2 = pack2(w3i[0], w3i[1]);
    const ull w4r2 = pack2(w4r[0], w4r[1]), w4i2 = pack2(w4i[0], w4i[1]);
    const ull nw4i2 = pack2(-w4i[0], -w4i[1]);
    const ull cr2  = pack2(cr[0], cr[1]),   nci2 = pack2(-ci[0], -ci[1]);
    const ull c1r2 = pack2(c1r[0], c1r[1]), nc1i2 = pack2(-c1i[0], -c1i[1]);
    const ull c2r2 = pack2(c2r[0], c2r[1]), nc2i2 = pack2(-c2i[0], -c2i[1]);
    const ull c3r2 = pack2(c3r[0], c3r[1]), nc3i2 = pack2(-c3i[0], -c3i[1]);

    // Toeplitz taps k_g = sum_n Re(c_n w_n^g), g = 0,1,2
    float k0 = cr[0] + cr[1];
    float k1 = c1r[0] + c1r[1];
    float k2 = c2r[0] + c2r[1];
    #pragma unroll
    for (int o = 16; o > 0; o >>= 1) {
        k0 += __shfl_xor_sync(0xffffffffu, k0, o);
        k1 += __shfl_xor_sync(0xffffffffu, k1, o);
        k2 += __shfl_xor_sync(0xffffffffu, k2, o);
    }

    // FiLM gains
    float cv   = cond[b * NCD + lane];
    float gacc = cv * film_W[h * NCD + lane];
    float bacc = cv * film_W[(NH + h) * NCD + lane];
    #pragma unroll
    for (int o = 16; o > 0; o >>= 1) {
        gacc += __shfl_xor_sync(0xffffffffu, gacc, o);
        bacc += __shfl_xor_sync(0xffffffffu, bacc, o);
    }
    gacc += film_b[h];
    bacc += film_b[NH + h];

    // branchless per-thread tap constants (d = lane & 3)
    const int d = lane & 3;
    const float Dh  = Dvec[h];
    const float kD  = Dh + ((d == 3) ? 0.0f : k0);
    const float k1t = (d == 1 || d == 2) ? k1 : 0.0f;
    const float k2t = (d == 2) ? k2 : 0.0f;
    const float rw  = res_w[h];

    const size_t base = (size_t)bh * NL + (size_t)c * CLEN;
    const float* ub = g_u + base;
    const float* xb = x + base;
    float*       ob = out + base;

    // entering state  (q_{-1} for this chunk)
    const ull* sp = g_s + ((size_t)(bh * NC + c)) * 64;
    ull qr = sp[lane];
    ull qi = sp[lane + 32];

    float u_cur = ub[lane];
    float x_cur = xb[lane];

    float2* U = Us[w];

    for (int l0 = 0; l0 < CLEN; l0 += 32) {
        float* P = Ps[w][(l0 >> 5) & 1];

        U[lane] = make_float2(u_cur, u_cur);

        int nn = (l0 + 32 < CLEN) ? (l0 + 32 + lane) : lane;
        float u_nx = ub[nn];
        float x_nx = xb[nn];

        __syncwarp();
        #pragma unroll
        for (int m = 0; m < 8; m++) {
            ulonglong2 p01 = *(const ulonglong2*)&U[4*m];
            ulonglong2 p23 = *(const ulonglong2*)&U[4*m + 2];
            // prep: r = w^3 u1 + w^2 u2 + w u3 + u4
            ull rr = fma2(w3r2, p01.x, fma2(w2r2, p01.y, fma2(w1r2, p23.x, p23.y)));
            ull ri = fma2(w3i2, p01.x, fma2(w2i2, p01.y, mul2(w1i2, p23.x)));
            // interior projections off entry state
            ull P1 = fma2(c1r2, qr, mul2(nc1i2, qi));
            ull P2 = fma2(c2r2, qr, mul2(nc2i2, qi));
            ull P3 = fma2(c3r2, qr, mul2(nc3i2, qi));
            // state update
            ull nqr = fma2(w4r2, qr, fma2(nw4i2, qi, rr));
            qi      = fma2(w4i2, qr, fma2(w4r2,  qi, ri));
            qr      = nqr;
            ull P4  = fma2(cr2, qr, mul2(nci2, qi));
            float2 v1 = unpack2(P1), v2 = unpack2(P2);
            float2 v3 = unpack2(P3), v4 = unpack2(P4);
            P[(4*m + 0)*PPAD + lane] = v1.x + v1.y;
            P[(4*m + 1)*PPAD + lane] = v2.x + v2.y;
            P[(4*m + 2)*PPAD + lane] = v3.x + v3.y;
            P[(4*m + 3)*PPAD + lane] = v4.x + v4.y;
        }
        __syncwarp();

        // reduce: thread `lane` sums its row with float4 loads (16B aligned)
        const float4* row = (const float4*)&P[lane * PPAD];
        float a0 = 0.f, a1 = 0.f, a2 = 0.f, a3 = 0.f;
        #pragma unroll
        for (int k = 0; k < 8; k++) {
            float4 v = row[k];
            a0 += v.x; a1 += v.y; a2 += v.z; a3 += v.w;
        }
        // branchless taps via shfl'd register u values
        float um1 = __shfl_up_sync(0xffffffffu, u_cur, 1);
        float um2 = __shfl_up_sync(0xffffffffu, u_cur, 2);
        float extra = kD * u_cur + k1t * um1 + k2t * um2;
        float y = (a0 + a1) + (a2 + a3) + extra;
        float o = gelu_exact(y * gacc + bacc) + x_cur * rw;
        ob[l0 + lane] = o;

        u_cur = u_nx;
        x_cur = x_nx;
    }
}

// =====================================================================
extern "C" void kernel_launch(void* const* d_in, const int* in_sizes, int n_in,
                              void* d_out, int out_size)
{
    (void)in_sizes; (void)n_in; (void)out_size;
    const float* x      = (const float*)d_in[0];
    const float* cond   = (const float*)d_in[1];
    const float* W      = (const float*)d_in[2];
    const float* b_lin  = (const float*)d_in[3];
    const float* log_dt = (const float*)d_in[4];
    const float* lAr    = (const float*)d_in[5];
    const float* Aim    = (const float*)d_in[6];
    const float* Cre    = (const float*)d_in[7];
    const float* Cim    = (const float*)d_in[8];
    const float* Dv     = (const float*)d_in[9];
    const float* fW     = (const float*)d_in[10];
    const float* fb     = (const float*)d_in[11];
    const float* rw     = (const float*)d_in[12];
    float* out = (float*)d_out;

    cudaFuncSetAttribute(premix_kernel,
                         cudaFuncAttributeMaxDynamicSharedMemorySize, 65536);

    wdup_kernel<<<1, 256>>>(W);
    premix_kernel<<<dim3(NL / 256, NB), 256, 65536>>>(x, b_lin);
    state_kernel<<<(NB * NH * (NC - 1)) / 4, 128>>>(log_dt, lAr, Aim);
    combine_kernel<<<(NB * NH) / 4, 128>>>(log_dt, lAr, Aim);
    scan_kernel<<<(NB * NH * NC) / 4, 128>>>(x, log_dt, lAr, Aim, Cre, Cim,
                                             Dv, cond, fW, fb, rw, out);
}

// round 16
// speedup vs baseline: 1.2575x; 1.2575x over previous
#include <cuda_runtime.h>
#include <math.h>

typedef unsigned long long ull;

#define NB 16
#define NH 64
#define NL 16384
#define NN 64
#define NCD 32
#define NC 8          // chunks per sequence
#define CLEN 2048     // NL / NC
#define PPAD 36       // P row stride (16B-aligned, conflict-free)

// scratch (static __device__ per harness rules)
__device__ float g_u[(size_t)NB * NH * NL];            // premixed+gelu input
__device__ ull   g_e[(size_t)NB * NH * (NC - 1) * 64]; // chunk end states (packed f32x2)
__device__ ull   g_s[(size_t)NB * NH * NC * 64];       // entering states

// ---------- packed f32x2 helpers ----------
__device__ __forceinline__ ull fma2(ull a, ull b, ull c) {
    ull d;
    asm("fma.rn.f32x2 %0, %1, %2, %3;" : "=l"(d) : "l"(a), "l"(b), "l"(c));
    return d;
}
__device__ __forceinline__ ull mul2(ull a, ull b) {
    ull d;
    asm("mul.rn.f32x2 %0, %1, %2;" : "=l"(d) : "l"(a), "l"(b));
    return d;
}
union F2U { float2 f; ull u; };
__device__ __forceinline__ ull pack2(float a, float b) { F2U t; t.f = make_float2(a, b); return t.u; }
__device__ __forceinline__ float2 unpack2(ull v) { F2U t; t.u = v; return t.f; }

__device__ __forceinline__ float gelu_exact(float v) {
    return 0.5f * v * (1.0f + erff(v * 0.7071067811865475f));
}

// 16-byte async copy global -> shared (Ampere+ cp.async)
__device__ __forceinline__ void cp_async16(void* smem_dst, const void* gmem_src) {
    unsigned saddr = (unsigned)__cvta_generic_to_shared(smem_dst);
    asm volatile("cp.async.ca.shared.global [%0], [%1], 16;"
                 :: "r"(saddr), "l"(gmem_src) : "memory");
}
__device__ __forceinline__ void cp_async_commit() {
    asm volatile("cp.async.commit_group;" ::: "memory");
}
__device__ __forceinline__ void cp_async_wait1() {
    asm volatile("cp.async.wait_group 1;" ::: "memory");
}
__device__ __forceinline__ void cp_async_wait0() {
    asm volatile("cp.async.wait_group 0;" ::: "memory");
}

// w = exp(dt*A) for the two states this lane owns
__device__ __forceinline__ void lane_w(int h, int lane,
                                       const float* __restrict__ log_dt,
                                       const float* __restrict__ log_A_real,
                                       const float* __restrict__ A_imag,
                                       float wr[2], float wi[2])
{
    const float dt = expf(log_dt[h]);
    #pragma unroll
    for (int s = 0; s < 2; s++) {
        int n = 2 * lane + s;
        float Ar = -expf(log_A_real[h * NN + n]);
        float Ai = A_imag[h * NN + n];
        float er = expf(Ar * dt);
        float sn, cs;
        sincosf(Ai * dt, &sn, &cs);
        wr[s] = er * cs;
        wi[s] = er * sn;
    }
}

// =====================================================================
// Kernel 1: premix  u = gelu(W x + b)
// x staged via cp.async in TWO commit groups (h 0..31, h 32..63):
// first half processed while second half lands. W duplicated into smem
// (broadcast LDS.128 in the inner loop — measured-best operand path).
// =====================================================================
__global__ __launch_bounds__(256, 2) void premix_kernel(
    const float* __restrict__ x, const float* __restrict__ W,
    const float* __restrict__ b_lin)
{
    extern __shared__ float2 sm2[];
    float2* xs = sm2;            // [NH][128] l-pairs
    float2* wd = sm2 + NH * 128; // [NH][NH] duplicated weights

    const int tid = threadIdx.x;
    const int b   = blockIdx.y;
    const int l0  = blockIdx.x * 256;

    // async-stage x in two halves: rows h = i>>6, 64 uint4 per row
    const float* xb = x + ((size_t)b * NH) * NL + l0;
    #pragma unroll
    for (int k = 0; k < 8; k++) {                    // h 0..31
        int i = tid + k * 256;
        int h = i >> 6, v = i & 63;
        cp_async16((char*)xs + h * 1024 + v * 16, xb + (size_t)h * NL + v * 4);
    }
    cp_async_commit();
    #pragma unroll
    for (int k = 8; k < 16; k++) {                   // h 32..63
        int i = tid + k * 256;
        int h = i >> 6, v = i & 63;
        cp_async16((char*)xs + h * 1024 + v * 16, xb + (size_t)h * NL + v * 4);
    }
    cp_async_commit();

    // W duplication overlaps the async copies
    for (int i = tid; i < NH * NH; i += 256) {
        float wv = W[i];
        wd[i] = make_float2(wv, wv);
    }

    cp_async_wait1();            // first half (h 0..31) complete
    __syncthreads();

    const int tg   = tid >> 5;
    const int lane = tid & 31;

    ull acc[8][4];
    #pragma unroll
    for (int j = 0; j < 8; j++)
        #pragma unroll
        for (int p = 0; p < 4; p++) acc[j][p] = 0ULL;

    // ---- first h-half while second half is still landing ----
    #pragma unroll 2
    for (int h = 0; h < 32; h += 2) {
        ull xp0[4], xp1[4];
        #pragma unroll
        for (int p = 0; p < 4; p++) {
            xp0[p] = *(const ull*)&xs[h * 128 + lane + 32 * p];
            xp1[p] = *(const ull*)&xs[(h + 1) * 128 + lane + 32 * p];
        }
        #pragma unroll
        for (int j = 0; j < 8; j++) {
            ulonglong2 wv2 = *(const ulonglong2*)&wd[(tg * 8 + j) * NH + h];
            #pragma unroll
            for (int p = 0; p < 4; p++) acc[j][p] = fma2(wv2.x, xp0[p], acc[j][p]);
            #pragma unroll
            for (int p = 0; p < 4; p++) acc[j][p] = fma2(wv2.y, xp1[p], acc[j][p]);
        }
    }

    cp_async_wait0();            // second half complete
    __syncthreads();

    // ---- second h-half ----
    #pragma unroll 2
    for (int h = 32; h < NH; h += 2) {
        ull xp0[4], xp1[4];
        #pragma unroll
        for (int p = 0; p < 4; p++) {
            xp0[p] = *(const ull*)&xs[h * 128 + lane + 32 * p];
            xp1[p] = *(const ull*)&xs[(h + 1) * 128 + lane + 32 * p];
        }
        #pragma unroll
        for (int j = 0; j < 8; j++) {
            ulonglong2 wv2 = *(const ulonglong2*)&wd[(tg * 8 + j) * NH + h];
            #pragma unroll
            for (int p = 0; p < 4; p++) acc[j][p] = fma2(wv2.x, xp0[p], acc[j][p]);
            #pragma unroll
            for (int p = 0; p < 4; p++) acc[j][p] = fma2(wv2.y, xp1[p], acc[j][p]);
        }
    }

    #pragma unroll
    for (int j = 0; j < 8; j++) {
        int g = tg * 8 + j;
        float bl = b_lin[g];
        float2* ub = (float2*)(g_u + ((size_t)b * NH + g) * NL + l0);
        #pragma unroll
        for (int p = 0; p < 4; p++) {
            float2 v = unpack2(acc[j][p]);
            ub[lane + 32 * p] = make_float2(gelu_exact(v.x + bl), gelu_exact(v.y + bl));
        }
    }
}

// =====================================================================
// Kernel 2: pass 1 — zero-init state recurrence per chunk (chunks 0..NC-2)
// 8-step grouped:  q' = w^8 q + (w^7 u1 + ... + w u7 + u8)
// =====================================================================
__global__ __launch_bounds__(128) void state_kernel(
    const float* __restrict__ log_dt, const float* __restrict__ log_A_real,
    const float* __restrict__ A_imag)
{
    __shared__ __align__(16) float2 Us[4][2][32];

    const int w    = threadIdx.x >> 5;
    const int lane = threadIdx.x & 31;
    const int idx  = blockIdx.x * 4 + w;
    const int bh   = idx / (NC - 1);
    const int c    = idx - bh * (NC - 1);
    const int h    = bh & 63;

    float wr[2], wi[2];
    lane_w(h, lane, log_dt, log_A_real, A_imag, wr, wi);

    float pr[8][2], pi[8][2];
    #pragma unroll
    for (int s = 0; s < 2; s++) { pr[0][s] = wr[s]; pi[0][s] = wi[s]; }
    #pragma unroll
    for (int k = 1; k < 8; k++) {
        #pragma unroll
        for (int s = 0; s < 2; s++) {
            pr[k][s] = pr[k-1][s] * wr[s] - pi[k-1][s] * wi[s];
            pi[k][s] = pr[k-1][s] * wi[s] + pi[k-1][s] * wr[s];
        }
    }
    const ull w1r2 = pack2(pr[0][0], pr[0][1]), w1i2 = pack2(pi[0][0], pi[0][1]);
    const ull w2r2 = pack2(pr[1][0], pr[1][1]), w2i2 = pack2(pi[1][0], pi[1][1]);
    const ull w3r2 = pack2(pr[2][0], pr[2][1]), w3i2 = pack2(pi[2][0], pi[2][1]);
    const ull w4r2 = pack2(pr[3][0], pr[3][1]), w4i2 = pack2(pi[3][0], pi[3][1]);
    const ull w5r2 = pack2(pr[4][0], pr[4][1]), w5i2 = pack2(pi[4][0], pi[4][1]);
    const ull w6r2 = pack2(pr[5][0], pr[5][1]), w6i2 = pack2(pi[5][0], pi[5][1]);
    const ull w7r2 = pack2(pr[6][0], pr[6][1]), w7i2 = pack2(pi[6][0], pi[6][1]);
    const ull w8r2 = pack2(pr[7][0], pr[7][1]), w8i2 = pack2(pi[7][0], pi[7][1]);
    const ull nw8i2 = pack2(-pi[7][0], -pi[7][1]);

    const float* ub = g_u + (size_t)bh * NL + (size_t)c * CLEN;

    float u_cur = ub[lane];
    ull qr = 0ULL, qi = 0ULL;

    for (int l0 = 0; l0 < CLEN; l0 += 32) {
        float2* U = Us[w][(l0 >> 5) & 1];
        U[lane] = make_float2(u_cur, u_cur);
        int nn = (l0 + 32 < CLEN) ? (l0 + 32 + lane) : lane;
        float u_nx = ub[nn];
        __syncwarp();
        #pragma unroll
        for (int m = 0; m < 4; m++) {
            ulonglong2 p01 = *(const ulonglong2*)&U[8*m];
            ulonglong2 p23 = *(const ulonglong2*)&U[8*m + 2];
            ulonglong2 p45 = *(const ulonglong2*)&U[8*m + 4];
            ulonglong2 p67 = *(const ulonglong2*)&U[8*m + 6];
            ull rr = fma2(w7r2, p01.x, fma2(w6r2, p01.y, fma2(w5r2, p23.x,
                     fma2(w4r2, p23.y, fma2(w3r2, p45.x, fma2(w2r2, p45.y,
                     fma2(w1r2, p67.x, p67.y)))))));
            ull ri = fma2(w7i2, p01.x, fma2(w6i2, p01.y, fma2(w5i2, p23.x,
                     fma2(w4i2, p23.y, fma2(w3i2, p45.x, fma2(w2i2, p45.y,
                     mul2(w1i2, p67.x)))))));
            ull nqr = fma2(w8r2, qr, fma2(nw8i2, qi, rr));
            qi      = fma2(w8i2, qr, fma2(w8r2,  qi, ri));
            qr      = nqr;
        }
        u_cur = u_nx;
    }

    ull* ep = g_e + ((size_t)(bh * (NC - 1) + c)) * 64;
    ep[lane]      = qr;
    ep[lane + 32] = qi;
}

// =====================================================================
// Kernel 3: pass 2 — serial combine over chunks (tiny)
// =====================================================================
__global__ __launch_bounds__(128) void combine_kernel(
    const float* __restrict__ log_dt, const float* __restrict__ log_A_real,
    const float* __restrict__ A_imag)
{
    const int w    = threadIdx.x >> 5;
    const int lane = threadIdx.x & 31;
    const int bh   = blockIdx.x * 4 + w;
    const int h    = bh & 63;

    float wr[2], wi[2];
    lane_w(h, lane, log_dt, log_A_real, A_imag, wr, wi);

    float tr[2] = {wr[0], wr[1]}, ti[2] = {wi[0], wi[1]};
    for (int k = 0; k < 11; k++) {
        #pragma unroll
        for (int s = 0; s < 2; s++) {
            float nr = tr[s]*tr[s] - ti[s]*ti[s];
            ti[s] = 2.0f*tr[s]*ti[s];
            tr[s] = nr;
        }
    }

    float sr[2] = {0.f, 0.f}, si[2] = {0.f, 0.f};
    for (int c = 0; c < NC; c++) {
        ull* sp = g_s + ((size_t)(bh * NC + c)) * 64;
        sp[lane]      = pack2(sr[0], sr[1]);
        sp[lane + 32] = pack2(si[0], si[1]);
        if (c < NC - 1) {
            const ull* ep = g_e + ((size_t)(bh * (NC - 1) + c)) * 64;
            float2 er = unpack2(ep[lane]);
            float2 ei = unpack2(ep[lane + 32]);
            float e_r[2] = {er.x, er.y}, e_i[2] = {ei.x, ei.y};
            #pragma unroll
            for (int s = 0; s < 2; s++) {
                float nr = tr[s]*sr[s] - ti[s]*si[s] + e_r[s];
                float ni = tr[s]*si[s] + ti[s]*sr[s] + e_i[s];
                sr[s] = nr; si[s] = ni;
            }
        }
    }
}

// =====================================================================
// Kernel 4: pass 3 — 4-step grouped scan (R12 math, measured best),
// single-buffered U, double-buffered P, branchless taps via shfl,
// fused FiLM + GELU + residual.
// =====================================================================
__global__ __launch_bounds__(128, 5) void scan_kernel(
    const float* __restrict__ x,
    const float* __restrict__ log_dt, const float* __restrict__ log_A_real,
    const float* __restrict__ A_imag, const float* __restrict__ C_re,
    const float* __restrict__ C_im,   const float* __restrict__ Dvec,
    const float* __restrict__ cond,   const float* __restrict__ film_W,
    const float* __restrict__ film_b, const float* __restrict__ res_w,
    float* __restrict__ out)
{
    __shared__ __align__(16) float2 Us[4][32];
    __shared__ __align__(16) float  Ps[4][2][32 * PPAD];

    const int w    = threadIdx.x >> 5;
    const int lane = threadIdx.x & 31;
    const int idx  = blockIdx.x * 4 + w;
    const int bh   = idx >> 3;
    const int c    = idx & 7;
    const int b    = bh >> 6;
    const int h    = bh & 63;

    float wr[2], wi[2];
    lane_w(h, lane, log_dt, log_A_real, A_imag, wr, wi);

    // coef c = 2*C*(w-1)/A
    float cr[2], ci[2];
    #pragma unroll
    for (int s = 0; s < 2; s++) {
        int n = 2 * lane + s;
        float Ar = -expf(log_A_real[h * NN + n]);
        float Ai = A_imag[h * NN + n];
        float Er = wr[s] - 1.0f, Ei = wi[s];
        float inv = 1.0f / (Ar*Ar + Ai*Ai);
        float Fr = (Er*Ar + Ei*Ai) * inv;
        float Fi = (Ei*Ar - Er*Ai) * inv;
        float Cr = C_re[h * NN + n], Ci = C_im[h * NN + n];
        cr[s] = 2.0f * (Cr*Fr - Ci*Fi);
        ci[s] = 2.0f * (Cr*Fi + Ci*Fr);
    }

    // w powers and projected coefs c*w^g
    float w2r[2], w2i[2], w3r[2], w3i[2], w4r[2], w4i[2];
    float c1r[2], c1i[2], c2r[2], c2i[2], c3r[2], c3i[2];
    #pragma unroll
    for (int s = 0; s < 2; s++) {
        w2r[s] = wr[s]*wr[s] - wi[s]*wi[s];   w2i[s] = 2.0f*wr[s]*wi[s];
        w3r[s] = w2r[s]*wr[s] - w2i[s]*wi[s]; w3i[s] = w2r[s]*wi[s] + w2i[s]*wr[s];
        w4r[s] = w2r[s]*w2r[s] - w2i[s]*w2i[s]; w4i[s] = 2.0f*w2r[s]*w2i[s];
        c1r[s] = cr[s]*wr[s]  - ci[s]*wi[s];  c1i[s] = cr[s]*wi[s]  + ci[s]*wr[s];
        c2r[s] = cr[s]*w2r[s] - ci[s]*w2i[s]; c2i[s] = cr[s]*w2i[s] + ci[s]*w2r[s];
        c3r[s] = cr[s]*w3r[s] - ci[s]*w3i[s]; c3i[s] = cr[s]*w3i[s] + ci[s]*w3r[s];
    }
    const ull w1r2 = pack2(wr[0], wr[1]),   w1i2 = pack2(wi[0], wi[1]);
    const ull w2r2 = pack2(w2r[0], w2r[1]), w2i2 = pack2(w2i[0], w2i[1]);
    const ull w3r2 = pack2(w3r[0], w3r[1]), w3i2 = pack2(w3i[0], w3i[1]);
    const ull w4r2 = pack2(w4r[0], w4r[1]), w4i2 = pack2(w4i[0], w4i[1]);
    const ull nw4i2 = pack2(-w4i[0], -w4i[1]);
    const ull cr2  = pack2(cr[0], cr[1]),   nci2 = pack2(-ci[0], -ci[1]);
    const ull c1r2 = pack2(c1r[0], c1r[1]), nc1i2 = pack2(-c1i[0], -c1i[1]);
    const ull c2r2 = pack2(c2r[0], c2r[1]), nc2i2 = pack2(-c2i[0], -c2i[1]);
    const ull c3r2 = pack2(c3r[0], c3r[1]), nc3i2 = pack2(-c3i[0], -c3i[1]);

    // Toeplitz taps k_g = sum_n Re(c_n w_n^g), g = 0,1,2
    float k0 = cr[0] + cr[1];
    float k1 = c1r[0] + c1r[1];
    float k2 = c2r[0] + c2r[1];
    #pragma unroll
    for (int o = 16; o > 0; o >>= 1) {
        k0 += __shfl_xor_sync(0xffffffffu, k0, o);
        k1 += __shfl_xor_sync(0xffffffffu, k1, o);
        k2 += __shfl_xor_sync(0xffffffffu, k2, o);
    }

    // FiLM gains
    float cv   = cond[b * NCD + lane];
    float gacc = cv * film_W[h * NCD + lane];
    float bacc = cv * film_W[(NH + h) * NCD + lane];
    #pragma unroll
    for (int o = 16; o > 0; o >>= 1) {
        gacc += __shfl_xor_sync(0xffffffffu, gacc, o);
        bacc += __shfl_xor_sync(0xffffffffu, bacc, o);
    }
    gacc += film_b[h];
    bacc += film_b[NH + h];

    // branchless per-thread tap constants (d = lane & 3)
    const int d = lane & 3;
    const float Dh  = Dvec[h];
    const float kD  = Dh + ((d == 3) ? 0.0f : k0);
    const float k1t = (d == 1 || d == 2) ? k1 : 0.0f;
    const float k2t = (d == 2) ? k2 : 0.0f;
    const float rw  = res_w[h];

    const size_t base = (size_t)bh * NL + (size_t)c * CLEN;
    const float* ub = g_u + base;
    const float* xb = x + base;
    float*       ob = out + base;

    // entering state  (q_{-1} for this chunk)
    const ull* sp = g_s + ((size_t)(bh * NC + c)) * 64;
    ull qr = sp[lane];
    ull qi = sp[lane + 32];

    float u_cur = ub[lane];
    float x_cur = xb[lane];

    float2* U = Us[w];

    for (int l0 = 0; l0 < CLEN; l0 += 32) {
        float* P = Ps[w][(l0 >> 5) & 1];

        U[lane] = make_float2(u_cur, u_cur);

        int nn = (l0 + 32 < CLEN) ? (l0 + 32 + lane) : lane;
        float u_nx = ub[nn];
        float x_nx = xb[nn];

        __syncwarp();
        #pragma unroll
        for (int m = 0; m < 8; m++) {
            ulonglong2 p01 = *(const ulonglong2*)&U[4*m];
            ulonglong2 p23 = *(const ulonglong2*)&U[4*m + 2];
            // prep: r = w^3 u1 + w^2 u2 + w u3 + u4
            ull rr = fma2(w3r2, p01.x, fma2(w2r2, p01.y, fma2(w1r2, p23.x, p23.y)));
            ull ri = fma2(w3i2, p01.x, fma2(w2i2, p01.y, mul2(w1i2, p23.x)));
            // interior projections off entry state
            ull P1 = fma2(c1r2, qr, mul2(nc1i2, qi));
            ull P2 = fma2(c2r2, qr, mul2(nc2i2, qi));
            ull P3 = fma2(c3r2, qr, mul2(nc3i2, qi));
            // state update
            ull nqr = fma2(w4r2, qr, fma2(nw4i2, qi, rr));
            qi      = fma2(w4i2, qr, fma2(w4r2,  qi, ri));
            qr      = nqr;
            ull P4  = fma2(cr2, qr, mul2(nci2, qi));
            float2 v1 = unpack2(P1), v2 = unpack2(P2);
            float2 v3 = unpack2(P3), v4 = unpack2(P4);
            P[(4*m + 0)*PPAD + lane] = v1.x + v1.y;
            P[(4*m + 1)*PPAD + lane] = v2.x + v2.y;
            P[(4*m + 2)*PPAD + lane] = v3.x + v3.y;
            P[(4*m + 3)*PPAD + lane] = v4.x + v4.y;
        }
        __syncwarp();

        // reduce: thread `lane` sums its row with float4 loads (16B aligned)
        const float4* row = (const float4*)&P[lane * PPAD];
        float a0 = 0.f, a1 = 0.f, a2 = 0.f, a3 = 0.f;
        #pragma unroll
        for (int k = 0; k < 8; k++) {
            float4 v = row[k];
            a0 += v.x; a1 += v.y; a2 += v.z; a3 += v.w;
        }
        // branchless taps via shfl'd register u values
        float um1 = __shfl_up_sync(0xffffffffu, u_cur, 1);
        float um2 = __shfl_up_sync(0xffffffffu, u_cur, 2);
        float extra = kD * u_cur + k1t * um1 + k2t * um2;
        float y = (a0 + a1) + (a2 + a3) + extra;
        float o = gelu_exact(y * gacc + bacc) + x_cur * rw;
        ob[l0 + lane] = o;

        u_cur = u_nx;
        x_cur = x_nx;
    }
}

// =====================================================================
extern "C" void kernel_launch(void* const* d_in, const int* in_sizes, int n_in,
                              void* d_out, int out_size)
{
    (void)in_sizes; (void)n_in; (void)out_size;
    const float* x      = (const float*)d_in[0];
    const float* cond   = (const float*)d_in[1];
    const float* W      = (const float*)d_in[2];
    const float* b_lin  = (const float*)d_in[3];
    const float* log_dt = (const float*)d_in[4];
    const float* lAr    = (const float*)d_in[5];
    const float* Aim    = (const float*)d_in[6];
    const float* Cre    = (const float*)d_in[7];
    const float* Cim    = (const float*)d_in[8];
    const float* Dv     = (const float*)d_in[9];
    const float* fW     = (const float*)d_in[10];
    const float* fb     = (const float*)d_in[11];
    const float* rw     = (const float*)d_in[12];
    float* out = (float*)d_out;

    cudaFuncSetAttribute(premix_kernel,
                         cudaFuncAttributeMaxDynamicSharedMemorySize, 98304);

    premix_kernel<<<dim3(NL / 256, NB), 256, 98304>>>(x, W, b_lin);
    state_kernel<<<(NB * NH * (NC - 1)) / 4, 128>>>(log_dt, lAr, Aim);
    combine_kernel<<<(NB * NH) / 4, 128>>>(log_dt, lAr, Aim);
    scan_kernel<<<(NB * NH * NC) / 4, 128>>>(x, log_dt, lAr, Aim, Cre, Cim,
                                             Dv, cond, fW, fb, rw, out);
}